// round 13
// baseline (speedup 1.0000x reference)
#include <cuda_runtime.h>
#include <cuda_fp16.h>
#include <cstdint>

#define B_  8
#define C_  256
#define HW_ 128
#define NE_ 20

// ---------------- device-global scratch (sanctioned; no runtime allocs) ----------------
__device__ float g_pooled[B_ * C_];
__device__ float g_piror[B_ * C_];
__device__ __align__(1024) float g_skip[(size_t)B_ * HW_ * HW_ * C_];   // NHWC fp32
// packed activations fp16: per pixel 256 halves (NHWC)
__device__ __align__(1024) __half g_actA[(size_t)B_ * HW_ * HW_ * 256];
__device__ __align__(1024) __half g_actB[(size_t)B_ * HW_ * HW_ * 256];
// packed weights fp16: [i*9+ky*3+kx][oc 256][ic 256]
__device__ __align__(1024) __half g_w1p[(size_t)27 * 256 * 256];
__device__ __align__(1024) __half g_w2p[(size_t)27 * 256 * 256];

// ---------------- PTX helpers ----------------
__device__ __forceinline__ uint32_t smem_u32(const void* p) {
    uint32_t a;
    asm("{ .reg .u64 t; cvta.to.shared.u64 t, %1; cvt.u32.u64 %0, t; }" : "=r"(a) : "l"(p));
    return a;
}
__device__ __forceinline__ void cp16(uint32_t dst, const void* src) {
    asm volatile("cp.async.cg.shared.global [%0], [%1], 16;" :: "r"(dst), "l"(src));
}
// zero-fill variant: src_size = 0 -> 16 bytes of zeros
__device__ __forceinline__ void cp16z(uint32_t dst, const void* src, int sz) {
    asm volatile("cp.async.cg.shared.global [%0], [%1], 16, %2;"
                 :: "r"(dst), "l"(src), "r"(sz));
}
__device__ __forceinline__ void ldsm4(uint32_t* r, uint32_t a) {
    asm volatile("ldmatrix.sync.aligned.m8n8.x4.shared.b16 {%0,%1,%2,%3}, [%4];"
                 : "=r"(r[0]), "=r"(r[1]), "=r"(r[2]), "=r"(r[3]) : "r"(a));
}
__device__ __forceinline__ void mma16816(float* c, const uint32_t* a, uint32_t b0, uint32_t b1) {
    asm volatile(
        "mma.sync.aligned.m16n8k16.row.col.f32.f16.f16.f32 "
        "{%0,%1,%2,%3}, {%4,%5,%6,%7}, {%8,%9}, {%0,%1,%2,%3};"
        : "+f"(c[0]), "+f"(c[1]), "+f"(c[2]), "+f"(c[3])
        : "r"(a[0]), "r"(a[1]), "r"(a[2]), "r"(a[3]), "r"(b0), "r"(b1));
}

// ---------------- small kernels ----------------
__global__ void pool_kernel(const float* __restrict__ x) {
    int bc = blockIdx.x;
    const float* p = x + (size_t)bc * (HW_ * HW_);
    float s = 0.f;
    for (int i = threadIdx.x; i < HW_ * HW_; i += 256) s += p[i];
    __shared__ float red[256];
    red[threadIdx.x] = s;
    __syncthreads();
    for (int o = 128; o > 0; o >>= 1) {
        if (threadIdx.x < o) red[threadIdx.x] += red[threadIdx.x + o];
        __syncthreads();
    }
    if (threadIdx.x == 0) g_pooled[bc] = red[0] * (1.0f / (HW_ * HW_));
}

__global__ void piror_kernel(const float* __restrict__ Wmap,
                             const float* __restrict__ proj_w,
                             const float* __restrict__ proj_b,
                             const float* __restrict__ embed,
                             const float* __restrict__ gumbel_u) {
    __shared__ float m[C_];
    __shared__ float sc[NE_];
    __shared__ int sidx;
    int tid = threadIdx.x;
    for (int b = 0; b < B_; b++) {
        float acc = 0.f;
        for (int c = 0; c < C_; c++)
            acc += Wmap[tid * C_ + c] * g_pooled[b * C_ + c];
        m[tid] = 1.0f / (1.0f + expf(-acc));
        __syncthreads();
        if (tid < NE_) {
            float l = proj_b[tid];
            for (int c = 0; c < C_; c++) l += proj_w[tid * C_ + c] * m[c];
            float u = gumbel_u[b * NE_ + tid];
            float g = -logf(-logf(u + 1e-10f) + 1e-10f);
            sc[tid] = l + g;
        }
        __syncthreads();
        if (tid == 0) {
            int best = 0;
            float bv = sc[0];
            for (int n = 1; n < NE_; n++)
                if (sc[n] > bv) { bv = sc[n]; best = n; }
            sidx = best;
        }
        __syncthreads();
        g_piror[b * C_ + tid] = embed[sidx * C_ + tid];
        __syncthreads();
    }
}

// NCHW fp32 + piror -> {skip NHWC fp32, packed fp16 activations}
__global__ void input_prep(const float* __restrict__ x) {
    __shared__ float tile[32][33];
    int tx = threadIdx.x, ty = threadIdx.y;          // 32 x 8
    int by = blockIdx.x;                             // b*128 + y
    int b = by >> 7, y = by & 127;
    int x0 = blockIdx.y * 32, c0 = blockIdx.z * 32;
#pragma unroll
    for (int i = 0; i < 4; i++) {
        int cl = ty * 4 + i;
        tile[cl][tx] = x[((size_t)(b * C_ + c0 + cl) * HW_ + y) * HW_ + x0 + tx];
    }
    __syncthreads();
#pragma unroll
    for (int i = 0; i < 4; i++) {
        int xl = ty * 4 + i;
        int c = c0 + tx;
        float v = tile[tx][xl] + g_piror[b * C_ + c];
        size_t pix = (size_t)(b * HW_ + y) * HW_ + x0 + xl;
        g_skip[pix * 256 + c] = v;
        g_actA[pix * 256 + c] = __float2half_rn(v);
    }
}

// [i][oc][ic][ky][kx] fp32 -> fp16 [tap27][oc][ic], both stacks
__global__ void weight_prep(const float* __restrict__ w1, const float* __restrict__ w2) {
    int idx = blockIdx.x * 256 + threadIdx.x;        // < 27*256*256
    int ic = idx & 255, oc = (idx >> 8) & 255, t9 = idx >> 16;
    int i = t9 / 9, tap = t9 - 9 * i;
    size_t src = (((size_t)(i * C_ + oc) * C_ + ic) * 9) + tap;
    g_w1p[idx] = __float2half_rn(w1[src]);
    g_w2p[idx] = __float2half_rn(w2[src]);
}

// ---------------- conv3x3 on HMMA fp16: 2 rows/CTA (M=256), N=128, 8 warps m64n64 ----------------
// Fragment double-buffering: load step t+1 frags while issuing step t MMAs.
// MODE 0: relu(conv(g_actA, w1)+b1) -> g_actB
// MODE 1: g_skip += conv(g_actB, w2)+b2; also -> g_actA
// MODE 2: like 1 but writes NCHW d_out
#define A_SUB   (130 * 128)              // one row sub-block (+2 halo rows), 64 ic x 2B
#define A_BYTES (2 * A_SUB)              // 33280
#define W_BYTES (384 * 128)              // 3 kx x 128 oc, 64 ic x 2B
#define STG     (A_BYTES + W_BYTES)      // 82432
#define SMEMSZ  (2 * STG)                // 164864
#define NTHR    256

template <int MODE>
__global__ void __launch_bounds__(NTHR, 1)
conv_hmma(const float* __restrict__ bias, float* __restrict__ dout, int widx) {
    extern __shared__ char sm[];
    const uint32_t sb = smem_u32(sm);
    const int tid = threadIdx.x, lane = tid & 31, wid = tid >> 5;   // 8 warps
    const int y0 = blockIdx.x * 2, ocb = blockIdx.y, b = blockIdx.z;

    const char* __restrict__ actb = (const char*)((MODE == 0) ? g_actA : g_actB);
    const char* __restrict__ wpb  = (const char*)((MODE == 0) ? g_w1p : g_w2p);

    // zero x-halo rows (local rows 0,129) of both sub-blocks, both buffers
    if (tid < 64) {
        int bufi = tid >> 5, sub_ = (tid >> 4) & 1, rr = (tid >> 3) & 1, seg = tid & 7;
        uint32_t addr = sb + bufi * STG + sub_ * A_SUB + (rr ? 129 : 0) * 128 + seg * 16;
        asm volatile("st.shared.v4.b32 [%0], {%1,%1,%1,%1};" :: "r"(addr), "r"(0) : "memory");
    }

    const int S = 12;                                // 3 ky x 4 ic-chunks

    auto load_stage = [&](int s, int buf) {
        int ky = s >> 2, c = s & 3;
        int r0 = y0 + ky - 1;
        int r1 = y0 + ky;
        uint32_t bb = sb + buf * STG;
        int t9 = widx * 9 + ky * 3;
        const char* base = actb + ((size_t)b * HW_ * HW_) * 512 + c * 128;
#pragma unroll
        for (int j = 0; j < 20; j++) {
            int id = j * NTHR + tid;
            if (id < 2048) {
                int rs = id >> 10;                   // 0 -> r0, 1 -> r1
                int px = (id >> 3) & 127, seg = id & 7;
                int row = rs ? r1 : r0;
                int ok = ((unsigned)row < HW_) ? 16 : 0;
                int rowc = (row < 0) ? 0 : ((row > 127) ? 127 : row);
                const char* src = base + ((size_t)rowc * HW_ + px) * 512 + seg * 16;
                uint32_t dst = bb + rs * A_SUB + (px + 1) * 128 +
                               ((seg * 16) ^ (((px + 1) & 7) << 4));
                cp16z(dst, src, ok);
            } else {
                int w = id - 2048;                   // < 3072
                int row = w >> 3, seg = w & 7;       // row = kx*128 + ocl
                int kx = row >> 7, ocl = row & 127;
                const char* src = (const char*)wpb +
                    ((((size_t)(t9 + kx) * 256 + ocb * 128 + ocl) * 256) + c * 64) * 2 +
                    seg * 16;
                uint32_t dst = bb + A_BYTES + row * 128 + ((seg * 16) ^ ((row & 7) << 4));
                cp16(dst, src);
            }
        }
        asm volatile("cp.async.commit_group;" ::: "memory");
    };

    // per-warp geometry: warp tile = m64 (px) x n64 (oc)
    // seg = wid>>1: sub = seg>>1 (output row), pxb = (seg&1)*64; wn = (wid&1)*64
    const int seg  = wid >> 1;
    const int sub  = seg >> 1;
    const int pxb  = (seg & 1) * 64;
    const int wn   = (wid & 1) * 64;
    const int aRow0 = pxb + (lane & 15);
    const int aCol = (lane >> 4) * 16;               // bytes
    const int wRowL = wn + ((lane >> 4) << 3) + (lane & 7);
    const int wKsel = ((lane >> 3) & 1) * 16;
    const uint32_t wSw = (uint32_t)((lane & 7) << 4);

    float acc[4][8][4];
#pragma unroll
    for (int mt = 0; mt < 4; mt++)
#pragma unroll
        for (int g = 0; g < 8; g++)
#pragma unroll
            for (int k = 0; k < 4; k++) acc[mt][g][k] = 0.f;

    // fragment load for inner step t (kx = t>>2, kh = t&3)
    uint32_t ah[2][4][4], bw[2][4][4];
    auto ldfrags = [&](uint32_t base, int t, int fbuf) {
        int kx = t >> 2, kh = t & 3;
        int prow = aRow0 + kx;
        uint32_t aSw = (uint32_t)((prow & 7) << 4);
        uint32_t aH = base + sub * A_SUB + prow * 128 +
                      (uint32_t)(((kh * 32) + aCol) ^ aSw);
#pragma unroll
        for (int mt = 0; mt < 4; mt++) ldsm4(ah[fbuf][mt], aH + mt * 16 * 128);
        uint32_t wAddr = base + A_BYTES + (kx * 128 + wRowL) * 128 +
                         (uint32_t)(((kh * 32) + wKsel) ^ wSw);
#pragma unroll
        for (int bt = 0; bt < 4; bt++) ldsm4(bw[fbuf][bt], wAddr + bt * 16 * 128);
    };

    load_stage(0, 0);
    load_stage(1, 1);
#pragma unroll 1
    for (int s = 0; s < S; s++) {
        if (s + 1 < S) {
            asm volatile("cp.async.wait_group 1;" ::: "memory");
        } else {
            asm volatile("cp.async.wait_group 0;" ::: "memory");
        }
        __syncthreads();
        uint32_t base = sb + (uint32_t)(s & 1) * STG;
        ldfrags(base, 0, 0);
#pragma unroll
        for (int t = 0; t < 12; t++) {
            if (t < 11) ldfrags(base, t + 1, (t + 1) & 1);
            int fb = t & 1;
#pragma unroll
            for (int mt = 0; mt < 4; mt++)
#pragma unroll
                for (int g = 0; g < 8; g++)
                    mma16816(acc[mt][g], ah[fb][mt], bw[fb][g >> 1][(g & 1) * 2],
                             bw[fb][g >> 1][(g & 1) * 2 + 1]);
        }
        __syncthreads();                             // all consumed before ring reuse
        if (s + 2 < S) load_stage(s + 2, s & 1);
    }

    // ---- epilogue ----
    const int r = lane >> 2, q = lane & 3;
    const int ocbase = ocb * 128 + wn;
    const int yout = y0 + sub;
    const size_t pixBase = (size_t)(b * HW_ + yout) * HW_;
#pragma unroll
    for (int mt = 0; mt < 4; mt++) {
        int px0 = pxb + mt * 16 + r;
#pragma unroll
        for (int g = 0; g < 8; g++) {
            int oc = ocbase + g * 8 + 2 * q;
            float bz0 = __ldg(&bias[oc]), bz1 = __ldg(&bias[oc + 1]);
#pragma unroll
            for (int hh = 0; hh < 2; hh++) {
                int px = px0 + hh * 8;
                float v0 = acc[mt][g][hh * 2 + 0] + bz0;
                float v1 = acc[mt][g][hh * 2 + 1] + bz1;
                size_t pix = pixBase + px;
                if (MODE == 0) {
                    v0 = fmaxf(v0, 0.f);
                    v1 = fmaxf(v1, 0.f);
                    *(__half2*)&g_actB[pix * 256 + oc] =
                        __halves2half2(__float2half_rn(v0), __float2half_rn(v1));
                } else {
                    float2 sk = *(const float2*)&g_skip[pix * 256 + oc];
                    v0 += sk.x;
                    v1 += sk.y;
                    if (MODE == 1) {
                        *(float2*)&g_skip[pix * 256 + oc] = make_float2(v0, v1);
                        *(__half2*)&g_actA[pix * 256 + oc] =
                            __halves2half2(__float2half_rn(v0), __float2half_rn(v1));
                    } else {
                        dout[((size_t)(b * C_ + oc) * HW_ + yout) * HW_ + px] = v0;
                        dout[((size_t)(b * C_ + oc + 1) * HW_ + yout) * HW_ + px] = v1;
                    }
                }
            }
        }
    }
}

// ---------------- launcher ----------------
extern "C" void kernel_launch(void* const* d_in, const int* in_sizes, int n_in,
                              void* d_out, int out_size) {
    const float* x        = (const float*)d_in[0];
    const float* gumbel_u = (const float*)d_in[1];
    const float* W_map    = (const float*)d_in[2];
    const float* proj_w   = (const float*)d_in[3];
    const float* proj_b   = (const float*)d_in[4];
    const float* embed    = (const float*)d_in[5];
    const float* res_w1   = (const float*)d_in[6];
    const float* res_b1   = (const float*)d_in[7];
    const float* res_w2   = (const float*)d_in[8];
    const float* res_b2   = (const float*)d_in[9];
    float* out = (float*)d_out;

    cudaFuncSetAttribute(conv_hmma<0>, cudaFuncAttributeMaxDynamicSharedMemorySize, SMEMSZ);
    cudaFuncSetAttribute(conv_hmma<1>, cudaFuncAttributeMaxDynamicSharedMemorySize, SMEMSZ);
    cudaFuncSetAttribute(conv_hmma<2>, cudaFuncAttributeMaxDynamicSharedMemorySize, SMEMSZ);

    pool_kernel<<<B_ * C_, 256>>>(x);
    piror_kernel<<<1, 256>>>(W_map, proj_w, proj_b, embed, gumbel_u);
    input_prep<<<dim3(B_ * HW_, 4, 8), dim3(32, 8)>>>(x);
    weight_prep<<<(27 * 256 * 256) / 256, 256>>>(res_w1, res_w2);

    dim3 cg(HW_ / 2, 2, B_);
    for (int i = 0; i < 3; i++) {
        conv_hmma<0><<<cg, NTHR, SMEMSZ>>>(res_b1 + i * C_, nullptr, i);
        if (i < 2)
            conv_hmma<1><<<cg, NTHR, SMEMSZ>>>(res_b2 + i * C_, nullptr, i);
        else
            conv_hmma<2><<<cg, NTHR, SMEMSZ>>>(res_b2 + i * C_, out, i);
    }
}

// round 14
// speedup vs baseline: 1.0566x; 1.0566x over previous
#include <cuda_runtime.h>
#include <cuda_fp16.h>
#include <cstdint>

#define B_  8
#define C_  256
#define HW_ 128
#define NE_ 20

// ---------------- device-global scratch (sanctioned; no runtime allocs) ----------------
__device__ float g_pooled[B_ * C_];
__device__ float g_piror[B_ * C_];
__device__ __align__(1024) float g_skip[(size_t)B_ * HW_ * HW_ * C_];   // NHWC fp32
// packed activations fp16: per pixel 256 halves (NHWC)
__device__ __align__(1024) __half g_actA[(size_t)B_ * HW_ * HW_ * 256];
__device__ __align__(1024) __half g_actB[(size_t)B_ * HW_ * HW_ * 256];
// packed weights fp16: [i*9+ky*3+kx][oc 256][ic 256]
__device__ __align__(1024) __half g_w1p[(size_t)27 * 256 * 256];
__device__ __align__(1024) __half g_w2p[(size_t)27 * 256 * 256];

// ---------------- PTX helpers ----------------
__device__ __forceinline__ uint32_t smem_u32(const void* p) {
    uint32_t a;
    asm("{ .reg .u64 t; cvta.to.shared.u64 t, %1; cvt.u32.u64 %0, t; }" : "=r"(a) : "l"(p));
    return a;
}
__device__ __forceinline__ void cp16(uint32_t dst, const void* src) {
    asm volatile("cp.async.cg.shared.global [%0], [%1], 16;" :: "r"(dst), "l"(src));
}
// zero-fill variant: src_size = 0 -> 16 bytes of zeros
__device__ __forceinline__ void cp16z(uint32_t dst, const void* src, int sz) {
    asm volatile("cp.async.cg.shared.global [%0], [%1], 16, %2;"
                 :: "r"(dst), "l"(src), "r"(sz));
}
__device__ __forceinline__ void ldsm4(uint32_t* r, uint32_t a) {
    asm volatile("ldmatrix.sync.aligned.m8n8.x4.shared.b16 {%0,%1,%2,%3}, [%4];"
                 : "=r"(r[0]), "=r"(r[1]), "=r"(r[2]), "=r"(r[3]) : "r"(a));
}
__device__ __forceinline__ void mma16816(float* c, const uint32_t* a, uint32_t b0, uint32_t b1) {
    asm volatile(
        "mma.sync.aligned.m16n8k16.row.col.f32.f16.f16.f32 "
        "{%0,%1,%2,%3}, {%4,%5,%6,%7}, {%8,%9}, {%0,%1,%2,%3};"
        : "+f"(c[0]), "+f"(c[1]), "+f"(c[2]), "+f"(c[3])
        : "r"(a[0]), "r"(a[1]), "r"(a[2]), "r"(a[3]), "r"(b0), "r"(b1));
}

// ---------------- small kernels ----------------
__global__ void pool_kernel(const float* __restrict__ x) {
    int bc = blockIdx.x;
    const float* p = x + (size_t)bc * (HW_ * HW_);
    float s = 0.f;
    for (int i = threadIdx.x; i < HW_ * HW_; i += 256) s += p[i];
    __shared__ float red[256];
    red[threadIdx.x] = s;
    __syncthreads();
    for (int o = 128; o > 0; o >>= 1) {
        if (threadIdx.x < o) red[threadIdx.x] += red[threadIdx.x + o];
        __syncthreads();
    }
    if (threadIdx.x == 0) g_pooled[bc] = red[0] * (1.0f / (HW_ * HW_));
}

__global__ void piror_kernel(const float* __restrict__ Wmap,
                             const float* __restrict__ proj_w,
                             const float* __restrict__ proj_b,
                             const float* __restrict__ embed,
                             const float* __restrict__ gumbel_u) {
    __shared__ float m[C_];
    __shared__ float sc[NE_];
    __shared__ int sidx;
    int tid = threadIdx.x;
    int b = blockIdx.x;
    float acc = 0.f;
    for (int c = 0; c < C_; c++)
        acc += Wmap[tid * C_ + c] * g_pooled[b * C_ + c];
    m[tid] = 1.0f / (1.0f + expf(-acc));
    __syncthreads();
    if (tid < NE_) {
        float l = proj_b[tid];
        for (int c = 0; c < C_; c++) l += proj_w[tid * C_ + c] * m[c];
        float u = gumbel_u[b * NE_ + tid];
        float g = -logf(-logf(u + 1e-10f) + 1e-10f);
        sc[tid] = l + g;
    }
    __syncthreads();
    if (tid == 0) {
        int best = 0;
        float bv = sc[0];
        for (int n = 1; n < NE_; n++)
            if (sc[n] > bv) { bv = sc[n]; best = n; }
        sidx = best;
    }
    __syncthreads();
    g_piror[b * C_ + tid] = embed[sidx * C_ + tid];
}

// NCHW fp32 + piror -> {skip NHWC fp32, packed fp16 activations}
__global__ void input_prep(const float* __restrict__ x) {
    __shared__ float tile[32][33];
    int tx = threadIdx.x, ty = threadIdx.y;          // 32 x 8
    int by = blockIdx.x;                             // b*128 + y
    int b = by >> 7, y = by & 127;
    int x0 = blockIdx.y * 32, c0 = blockIdx.z * 32;
#pragma unroll
    for (int i = 0; i < 4; i++) {
        int cl = ty * 4 + i;
        tile[cl][tx] = x[((size_t)(b * C_ + c0 + cl) * HW_ + y) * HW_ + x0 + tx];
    }
    __syncthreads();
#pragma unroll
    for (int i = 0; i < 4; i++) {
        int xl = ty * 4 + i;
        int c = c0 + tx;
        float v = tile[tx][xl] + g_piror[b * C_ + c];
        size_t pix = (size_t)(b * HW_ + y) * HW_ + x0 + xl;
        g_skip[pix * 256 + c] = v;
        g_actA[pix * 256 + c] = __float2half_rn(v);
    }
}

// [i][oc][ic][ky][kx] fp32 -> fp16 [tap27][oc][ic], both stacks
__global__ void weight_prep(const float* __restrict__ w1, const float* __restrict__ w2) {
    int idx = blockIdx.x * 256 + threadIdx.x;        // < 27*256*256
    int ic = idx & 255, oc = (idx >> 8) & 255, t9 = idx >> 16;
    int i = t9 / 9, tap = t9 - 9 * i;
    size_t src = (((size_t)(i * C_ + oc) * C_ + ic) * 9) + tap;
    g_w1p[idx] = __float2half_rn(w1[src]);
    g_w2p[idx] = __float2half_rn(w2[src]);
}

// ---------------- conv3x3 HMMA fp16: CTA = 2 rows (M=256) x 64 oc, 16 warps m32n32 ----------
// 3-buffer ring, ONE sync per stage; per-warp fragment double-buffering.
// MODE 0: relu(conv(g_actA, w1)+b1) -> g_actB
// MODE 1: g_skip += conv(g_actB, w2)+b2; also -> g_actA
// MODE 2: like 1 but writes NCHW d_out
#define A_SUB   (130 * 128)              // one row sub-block (+2 halo rows), 64 ic x 2B
#define A_BYTES (2 * A_SUB)              // 33280
#define W_BYTES (192 * 128)              // 3 kx x 64 oc, 64 ic x 2B = 24576
#define STG     (A_BYTES + W_BYTES)      // 57856
#define NBUF    3
#define SMEMSZ  (NBUF * STG)             // 173568
#define NTHR    512

template <int MODE>
__global__ void __launch_bounds__(NTHR, 1)
conv_hmma(const float* __restrict__ bias, float* __restrict__ dout, int widx) {
    extern __shared__ char sm[];
    const uint32_t sb = smem_u32(sm);
    const int tid = threadIdx.x, lane = tid & 31, wid = tid >> 5;   // 16 warps
    const int y0 = blockIdx.x * 2, ocb = blockIdx.y, b = blockIdx.z;

    const char* __restrict__ actb = (const char*)((MODE == 0) ? g_actA : g_actB);
    const char* __restrict__ wpb  = (const char*)((MODE == 0) ? g_w1p : g_w2p);

    // zero x-halo rows (local rows 0,129) of both sub-blocks, all 3 buffers
    if (tid < 96) {
        int bufi = tid >> 5, sub_ = (tid >> 4) & 1, rr = (tid >> 3) & 1, seg = tid & 7;
        uint32_t addr = sb + bufi * STG + sub_ * A_SUB + (rr ? 129 : 0) * 128 + seg * 16;
        asm volatile("st.shared.v4.b32 [%0], {%1,%1,%1,%1};" :: "r"(addr), "r"(0) : "memory");
    }

    const int S = 12;                                // 3 ky x 4 ic-chunks

    auto load_stage = [&](int s, int buf) {
        int ky = s >> 2, c = s & 3;
        int r0 = y0 + ky - 1;
        int r1 = y0 + ky;
        uint32_t bb = sb + buf * STG;
        int t9 = widx * 9 + ky * 3;
        const char* base = actb + ((size_t)b * HW_ * HW_) * 512 + c * 128;
#pragma unroll
        for (int j = 0; j < 7; j++) {
            int id = j * NTHR + tid;
            if (id < 2048) {
                int rs = id >> 10;                   // 0 -> r0, 1 -> r1
                int px = (id >> 3) & 127, seg = id & 7;
                int row = rs ? r1 : r0;
                int ok = ((unsigned)row < HW_) ? 16 : 0;
                int rowc = (row < 0) ? 0 : ((row > 127) ? 127 : row);
                const char* src = base + ((size_t)rowc * HW_ + px) * 512 + seg * 16;
                uint32_t dst = bb + rs * A_SUB + (px + 1) * 128 +
                               ((seg * 16) ^ (((px + 1) & 7) << 4));
                cp16z(dst, src, ok);
            } else if (id < 3584) {
                int w = id - 2048;                   // < 1536
                int row = w >> 3, seg = w & 7;       // row = kx*64 + ocl
                int kx = row >> 6, ocl = row & 63;
                const char* src = (const char*)wpb +
                    ((((size_t)(t9 + kx) * 256 + ocb * 64 + ocl) * 256) + c * 64) * 2 +
                    seg * 16;
                uint32_t dst = bb + A_BYTES + row * 128 + ((seg * 16) ^ ((row & 7) << 4));
                cp16(dst, src);
            }
        }
        asm volatile("cp.async.commit_group;" ::: "memory");
    };

    // per-warp geometry: warp tile m32 (px) x n32 (oc)
    // nsl = wid & 1 -> oc 32-half; msl = wid >> 1 (0..7): sub = msl>>2, pxb = (msl&3)*32
    const int nsl = wid & 1;
    const int msl = wid >> 1;
    const int sub = msl >> 2;
    const int pxb = (msl & 3) * 32;
    const int wn  = nsl * 32;
    const int aRow0 = pxb + (lane & 15);
    const int aCol = (lane >> 4) * 16;               // bytes
    const int wRowL = wn + ((lane >> 4) << 3) + (lane & 7);
    const int wKsel = ((lane >> 3) & 1) * 16;
    const uint32_t wSw = (uint32_t)((lane & 7) << 4);

    float acc[2][4][4];
#pragma unroll
    for (int mt = 0; mt < 2; mt++)
#pragma unroll
        for (int g = 0; g < 4; g++)
#pragma unroll
            for (int k = 0; k < 4; k++) acc[mt][g][k] = 0.f;

    // fragment buffers (double-buffered)
    uint32_t ah[2][2][4], bw[2][2][4];
    auto ldfrags = [&](uint32_t base, int t, int fb) {
        int kx = t >> 2, kh = t & 3;
        int prow = aRow0 + kx;
        uint32_t aSw = (uint32_t)((prow & 7) << 4);
        uint32_t aH = base + sub * A_SUB + prow * 128 +
                      (uint32_t)(((kh * 32) + aCol) ^ aSw);
        ldsm4(ah[fb][0], aH);
        ldsm4(ah[fb][1], aH + 16 * 128);
        uint32_t wA = base + A_BYTES + (kx * 64 + wRowL) * 128 +
                      (uint32_t)(((kh * 32) + wKsel) ^ wSw);
        ldsm4(bw[fb][0], wA);
        ldsm4(bw[fb][1], wA + 16 * 128);
    };

    load_stage(0, 0);
    load_stage(1, 1);
#pragma unroll 1
    for (int s = 0; s < S; s++) {
        if (s + 1 < S) {
            asm volatile("cp.async.wait_group 1;" ::: "memory");
        } else {
            asm volatile("cp.async.wait_group 0;" ::: "memory");
        }
        __syncthreads();                 // everyone done with stage s-1, load s complete
        if (s + 2 < S) load_stage(s + 2, (s + 2) % NBUF);   // targets buf (s-1)%3: safe
        uint32_t base = sb + (uint32_t)(s % NBUF) * STG;
        ldfrags(base, 0, 0);
#pragma unroll
        for (int t = 0; t < 12; t++) {
            if (t < 11) ldfrags(base, t + 1, (t + 1) & 1);
            int fb = t & 1;
#pragma unroll
            for (int mt = 0; mt < 2; mt++)
#pragma unroll
                for (int g = 0; g < 4; g++)
                    mma16816(acc[mt][g], ah[fb][mt], bw[fb][g >> 1][(g & 1) * 2],
                             bw[fb][g >> 1][(g & 1) * 2 + 1]);
        }
    }

    // ---- epilogue ----
    const int r = lane >> 2, q = lane & 3;
    const int ocbase = ocb * 64 + wn;
    const int yout = y0 + sub;
    const size_t pixBase = (size_t)(b * HW_ + yout) * HW_;
#pragma unroll
    for (int mt = 0; mt < 2; mt++) {
        int px0 = pxb + mt * 16 + r;
#pragma unroll
        for (int g = 0; g < 4; g++) {
            int oc = ocbase + g * 8 + 2 * q;
            float bz0 = __ldg(&bias[oc]), bz1 = __ldg(&bias[oc + 1]);
#pragma unroll
            for (int hh = 0; hh < 2; hh++) {
                int px = px0 + hh * 8;
                float v0 = acc[mt][g][hh * 2 + 0] + bz0;
                float v1 = acc[mt][g][hh * 2 + 1] + bz1;
                size_t pix = pixBase + px;
                if (MODE == 0) {
                    v0 = fmaxf(v0, 0.f);
                    v1 = fmaxf(v1, 0.f);
                    *(__half2*)&g_actB[pix * 256 + oc] =
                        __halves2half2(__float2half_rn(v0), __float2half_rn(v1));
                } else {
                    float2 sk = *(const float2*)&g_skip[pix * 256 + oc];
                    v0 += sk.x;
                    v1 += sk.y;
                    if (MODE == 1) {
                        *(float2*)&g_skip[pix * 256 + oc] = make_float2(v0, v1);
                        *(__half2*)&g_actA[pix * 256 + oc] =
                            __halves2half2(__float2half_rn(v0), __float2half_rn(v1));
                    } else {
                        dout[((size_t)(b * C_ + oc) * HW_ + yout) * HW_ + px] = v0;
                        dout[((size_t)(b * C_ + oc + 1) * HW_ + yout) * HW_ + px] = v1;
                    }
                }
            }
        }
    }
}

// ---------------- launcher ----------------
extern "C" void kernel_launch(void* const* d_in, const int* in_sizes, int n_in,
                              void* d_out, int out_size) {
    const float* x        = (const float*)d_in[0];
    const float* gumbel_u = (const float*)d_in[1];
    const float* W_map    = (const float*)d_in[2];
    const float* proj_w   = (const float*)d_in[3];
    const float* proj_b   = (const float*)d_in[4];
    const float* embed    = (const float*)d_in[5];
    const float* res_w1   = (const float*)d_in[6];
    const float* res_b1   = (const float*)d_in[7];
    const float* res_w2   = (const float*)d_in[8];
    const float* res_b2   = (const float*)d_in[9];
    float* out = (float*)d_out;

    cudaFuncSetAttribute(conv_hmma<0>, cudaFuncAttributeMaxDynamicSharedMemorySize, SMEMSZ);
    cudaFuncSetAttribute(conv_hmma<1>, cudaFuncAttributeMaxDynamicSharedMemorySize, SMEMSZ);
    cudaFuncSetAttribute(conv_hmma<2>, cudaFuncAttributeMaxDynamicSharedMemorySize, SMEMSZ);

    pool_kernel<<<B_ * C_, 256>>>(x);
    piror_kernel<<<B_, 256>>>(W_map, proj_w, proj_b, embed, gumbel_u);
    input_prep<<<dim3(B_ * HW_, 4, 8), dim3(32, 8)>>>(x);
    weight_prep<<<(27 * 256 * 256) / 256, 256>>>(res_w1, res_w2);

    dim3 cg(HW_ / 2, 4, B_);
    for (int i = 0; i < 3; i++) {
        conv_hmma<0><<<cg, NTHR, SMEMSZ>>>(res_b1 + i * C_, nullptr, i);
        if (i < 2)
            conv_hmma<1><<<cg, NTHR, SMEMSZ>>>(res_b2 + i * C_, nullptr, i);
        else
            conv_hmma<2><<<cg, NTHR, SMEMSZ>>>(res_b2 + i * C_, out, i);
    }
}

// round 17
// speedup vs baseline: 1.0719x; 1.0145x over previous
#include <cuda_runtime.h>
#include <cuda_fp16.h>
#include <cstdint>

#define B_  8
#define C_  256
#define HW_ 128
#define NE_ 20

// ---------------- device-global scratch (sanctioned; no runtime allocs) ----------------
__device__ float g_pooled[B_ * C_];
__device__ float g_piror[B_ * C_];
__device__ __align__(1024) float g_skip[(size_t)B_ * HW_ * HW_ * C_];   // NHWC fp32
// packed activations fp16: per pixel 256 halves (NHWC)
__device__ __align__(1024) __half g_actA[(size_t)B_ * HW_ * HW_ * 256];
__device__ __align__(1024) __half g_actB[(size_t)B_ * HW_ * HW_ * 256];
// packed weights fp16: [i*9+ky*3+kx][oc 256][ic 256]
__device__ __align__(1024) __half g_w1p[(size_t)27 * 256 * 256];
__device__ __align__(1024) __half g_w2p[(size_t)27 * 256 * 256];

// ---------------- PTX helpers ----------------
__device__ __forceinline__ uint32_t smem_u32(const void* p) {
    uint32_t a;
    asm("{ .reg .u64 t; cvta.to.shared.u64 t, %1; cvt.u32.u64 %0, t; }" : "=r"(a) : "l"(p));
    return a;
}
__device__ __forceinline__ void cp16(uint32_t dst, const void* src) {
    asm volatile("cp.async.cg.shared.global [%0], [%1], 16;" :: "r"(dst), "l"(src));
}
// zero-fill variant: src_size = 0 -> 16 bytes of zeros
__device__ __forceinline__ void cp16z(uint32_t dst, const void* src, int sz) {
    asm volatile("cp.async.cg.shared.global [%0], [%1], 16, %2;"
                 :: "r"(dst), "l"(src), "r"(sz));
}
__device__ __forceinline__ void ldsm4(uint32_t* r, uint32_t a) {
    asm volatile("ldmatrix.sync.aligned.m8n8.x4.shared.b16 {%0,%1,%2,%3}, [%4];"
                 : "=r"(r[0]), "=r"(r[1]), "=r"(r[2]), "=r"(r[3]) : "r"(a));
}
__device__ __forceinline__ void mma16816(float* c, const uint32_t* a, uint32_t b0, uint32_t b1) {
    asm volatile(
        "mma.sync.aligned.m16n8k16.row.col.f32.f16.f16.f32 "
        "{%0,%1,%2,%3}, {%4,%5,%6,%7}, {%8,%9}, {%0,%1,%2,%3};"
        : "+f"(c[0]), "+f"(c[1]), "+f"(c[2]), "+f"(c[3])
        : "r"(a[0]), "r"(a[1]), "r"(a[2]), "r"(a[3]), "r"(b0), "r"(b1));
}

// ---------------- small kernels ----------------
__global__ void pool_kernel(const float* __restrict__ x) {
    int bc = blockIdx.x;
    const float* p = x + (size_t)bc * (HW_ * HW_);
    float s = 0.f;
    for (int i = threadIdx.x; i < HW_ * HW_; i += 256) s += p[i];
    __shared__ float red[256];
    red[threadIdx.x] = s;
    __syncthreads();
    for (int o = 128; o > 0; o >>= 1) {
        if (threadIdx.x < o) red[threadIdx.x] += red[threadIdx.x + o];
        __syncthreads();
    }
    if (threadIdx.x == 0) g_pooled[bc] = red[0] * (1.0f / (HW_ * HW_));
}

__global__ void piror_kernel(const float* __restrict__ Wmap,
                             const float* __restrict__ proj_w,
                             const float* __restrict__ proj_b,
                             const float* __restrict__ embed,
                             const float* __restrict__ gumbel_u) {
    __shared__ float m[C_];
    __shared__ float sc[NE_];
    __shared__ int sidx;
    int tid = threadIdx.x;
    int b = blockIdx.x;
    float acc = 0.f;
    for (int c = 0; c < C_; c++)
        acc += Wmap[tid * C_ + c] * g_pooled[b * C_ + c];
    m[tid] = 1.0f / (1.0f + expf(-acc));
    __syncthreads();
    if (tid < NE_) {
        float l = proj_b[tid];
        for (int c = 0; c < C_; c++) l += proj_w[tid * C_ + c] * m[c];
        float u = gumbel_u[b * NE_ + tid];
        float g = -logf(-logf(u + 1e-10f) + 1e-10f);
        sc[tid] = l + g;
    }
    __syncthreads();
    if (tid == 0) {
        int best = 0;
        float bv = sc[0];
        for (int n = 1; n < NE_; n++)
            if (sc[n] > bv) { bv = sc[n]; best = n; }
        sidx = best;
    }
    __syncthreads();
    g_piror[b * C_ + tid] = embed[sidx * C_ + tid];
}

// NCHW fp32 + piror -> {skip NHWC fp32, packed fp16 activations}
__global__ void input_prep(const float* __restrict__ x) {
    __shared__ float tile[32][33];
    int tx = threadIdx.x, ty = threadIdx.y;          // 32 x 8
    int by = blockIdx.x;                             // b*128 + y
    int b = by >> 7, y = by & 127;
    int x0 = blockIdx.y * 32, c0 = blockIdx.z * 32;
#pragma unroll
    for (int i = 0; i < 4; i++) {
        int cl = ty * 4 + i;
        tile[cl][tx] = x[((size_t)(b * C_ + c0 + cl) * HW_ + y) * HW_ + x0 + tx];
    }
    __syncthreads();
#pragma unroll
    for (int i = 0; i < 4; i++) {
        int xl = ty * 4 + i;
        int c = c0 + tx;
        float v = tile[tx][xl] + g_piror[b * C_ + c];
        size_t pix = (size_t)(b * HW_ + y) * HW_ + x0 + xl;
        g_skip[pix * 256 + c] = v;
        g_actA[pix * 256 + c] = __float2half_rn(v);
    }
}

// [i][oc][ic][ky][kx] fp32 -> fp16 [tap27][oc][ic], both stacks
__global__ void weight_prep(const float* __restrict__ w1, const float* __restrict__ w2) {
    int idx = blockIdx.x * 256 + threadIdx.x;        // < 27*256*256
    int ic = idx & 255, oc = (idx >> 8) & 255, t9 = idx >> 16;
    int i = t9 / 9, tap = t9 - 9 * i;
    size_t src = (((size_t)(i * C_ + oc) * C_ + ic) * 9) + tap;
    g_w1p[idx] = __float2half_rn(w1[src]);
    g_w2p[idx] = __float2half_rn(w2[src]);
}

// ---------------- conv3x3 HMMA fp16: CTA = 2 rows (M=256) x 64 oc, 16 warps m32n32 ----------
// 3-buffer ring, ONE sync per stage, frag double-buffering,
// cp.async issue INTERLEAVED into the MMA inner loop (1 op/thread/iter, t=0..6).
// MODE 0: relu(conv(g_actA, w1)+b1) -> g_actB
// MODE 1: g_skip += conv(g_actB, w2)+b2; also -> g_actA
// MODE 2: like 1 but writes NCHW d_out
#define A_SUB   (130 * 128)              // one row sub-block (+2 halo rows), 64 ic x 2B
#define A_BYTES (2 * A_SUB)              // 33280
#define W_BYTES (192 * 128)              // 3 kx x 64 oc, 64 ic x 2B = 24576
#define STG     (A_BYTES + W_BYTES)      // 57856
#define NBUF    3
#define SMEMSZ  (NBUF * STG)             // 173568
#define NTHR    512

template <int MODE>
__global__ void __launch_bounds__(NTHR, 1)
conv_hmma(const float* __restrict__ bias, float* __restrict__ dout, int widx) {
    extern __shared__ char sm[];
    const uint32_t sb = smem_u32(sm);
    const int tid = threadIdx.x, lane = tid & 31, wid = tid >> 5;   // 16 warps
    const int y0 = blockIdx.x * 2, ocb = blockIdx.y, b = blockIdx.z;

    const char* __restrict__ actb = (const char*)((MODE == 0) ? g_actA : g_actB);
    const char* __restrict__ wpb  = (const char*)((MODE == 0) ? g_w1p : g_w2p);

    // zero x-halo rows (local rows 0,129) of both sub-blocks, all 3 buffers
    if (tid < 96) {
        int bufi = tid >> 5, sub_ = (tid >> 4) & 1, rr = (tid >> 3) & 1, seg = tid & 7;
        uint32_t addr = sb + bufi * STG + sub_ * A_SUB + (rr ? 129 : 0) * 128 + seg * 16;
        asm volatile("st.shared.v4.b32 [%0], {%1,%1,%1,%1};" :: "r"(addr), "r"(0) : "memory");
    }

    const int S = 12;                                // 3 ky x 4 ic-chunks

    // issue ONE cp.async (chunk j, j = 0..6) of stage s into buffer buf
    auto load_chunk = [&](int s, int buf, int j) {
        int ky = s >> 2, c = s & 3;
        uint32_t bb = sb + buf * STG;
        int id = j * NTHR + tid;
        if (id < 2048) {
            int rs = id >> 10;                       // 0 -> row r0, 1 -> row r1
            int px = (id >> 3) & 127, seg = id & 7;
            int row = y0 + ky - 1 + rs;
            int ok = ((unsigned)row < HW_) ? 16 : 0;
            int rowc = (row < 0) ? 0 : ((row > 127) ? 127 : row);
            const char* src = actb + ((size_t)(b * HW_ + rowc) * HW_ + px) * 512 +
                              c * 128 + seg * 16;
            uint32_t dst = bb + rs * A_SUB + (px + 1) * 128 +
                           ((seg * 16) ^ (((px + 1) & 7) << 4));
            cp16z(dst, src, ok);
        } else if (id < 3584) {
            int w = id - 2048;                       // < 1536
            int row = w >> 3, seg = w & 7;           // row = kx*64 + ocl
            int kx = row >> 6, ocl = row & 63;
            int t9 = widx * 9 + ky * 3;
            const char* src = (const char*)wpb +
                ((((size_t)(t9 + kx) * 256 + ocb * 64 + ocl) * 256) + c * 64) * 2 +
                seg * 16;
            uint32_t dst = bb + A_BYTES + row * 128 + ((seg * 16) ^ ((row & 7) << 4));
            cp16(dst, src);
        }
    };
    auto load_stage = [&](int s, int buf) {
#pragma unroll
        for (int j = 0; j < 7; j++) load_chunk(s, buf, j);
        asm volatile("cp.async.commit_group;" ::: "memory");
    };

    // per-warp geometry: warp tile m32 (px) x n32 (oc)
    const int nsl = wid & 1;
    const int msl = wid >> 1;
    const int sub = msl >> 2;
    const int pxb = (msl & 3) * 32;
    const int wn  = nsl * 32;
    const int aRow0 = pxb + (lane & 15);
    const int aCol = (lane >> 4) * 16;               // bytes
    const int wRowL = wn + ((lane >> 4) << 3) + (lane & 7);
    const int wKsel = ((lane >> 3) & 1) * 16;
    const uint32_t wSw = (uint32_t)((lane & 7) << 4);

    float acc[2][4][4];
#pragma unroll
    for (int mt = 0; mt < 2; mt++)
#pragma unroll
        for (int g = 0; g < 4; g++)
#pragma unroll
            for (int k = 0; k < 4; k++) acc[mt][g][k] = 0.f;

    // fragment buffers (double-buffered)
    uint32_t ah[2][2][4], bw[2][2][4];
    auto ldfrags = [&](uint32_t base, int t, int fb) {
        int kx = t >> 2, kh = t & 3;
        int prow = aRow0 + kx;
        uint32_t aSw = (uint32_t)((prow & 7) << 4);
        uint32_t aH = base + sub * A_SUB + prow * 128 +
                      (uint32_t)(((kh * 32) + aCol) ^ aSw);
        ldsm4(ah[fb][0], aH);
        ldsm4(ah[fb][1], aH + 16 * 128);
        uint32_t wA = base + A_BYTES + (kx * 64 + wRowL) * 128 +
                      (uint32_t)(((kh * 32) + wKsel) ^ wSw);
        ldsm4(bw[fb][0], wA);
        ldsm4(bw[fb][1], wA + 16 * 128);
    };

    load_stage(0, 0);
    load_stage(1, 1);
#pragma unroll 1
    for (int s = 0; s < S; s++) {
        if (s + 1 < S) {
            asm volatile("cp.async.wait_group 1;" ::: "memory");
        } else {
            asm volatile("cp.async.wait_group 0;" ::: "memory");
        }
        __syncthreads();             // stage s data ready; buffer (s+2)%3 = (s-1)%3 drained
        uint32_t base = sb + (uint32_t)(s % NBUF) * STG;
        const bool pre = (s + 2 < S);
        const int nbuf2 = (s + 2) % NBUF;
        ldfrags(base, 0, 0);
#pragma unroll
        for (int t = 0; t < 12; t++) {
            if (pre && t < 7) load_chunk(s + 2, nbuf2, t);      // interleaved issue
            if (pre && t == 7)
                asm volatile("cp.async.commit_group;" ::: "memory");
            if (t < 11) ldfrags(base, t + 1, (t + 1) & 1);
            int fb = t & 1;
#pragma unroll
            for (int mt = 0; mt < 2; mt++)
#pragma unroll
                for (int g = 0; g < 4; g++)
                    mma16816(acc[mt][g], ah[fb][mt], bw[fb][g >> 1][(g & 1) * 2],
                             bw[fb][g >> 1][(g & 1) * 2 + 1]);
        }
    }

    // ---- epilogue ----
    const int r = lane >> 2, q = lane & 3;
    const int ocbase = ocb * 64 + wn;
    const int yout = y0 + sub;
    const size_t pixBase = (size_t)(b * HW_ + yout) * HW_;
#pragma unroll
    for (int mt = 0; mt < 2; mt++) {
        int px0 = pxb + mt * 16 + r;
#pragma unroll
        for (int g = 0; g < 4; g++) {
            int oc = ocbase + g * 8 + 2 * q;
            float bz0 = __ldg(&bias[oc]), bz1 = __ldg(&bias[oc + 1]);
#pragma unroll
            for (int hh = 0; hh < 2; hh++) {
                int px = px0 + hh * 8;
                float v0 = acc[mt][g][hh * 2 + 0] + bz0;
                float v1 = acc[mt][g][hh * 2 + 1] + bz1;
                size_t pix = pixBase + px;
                if (MODE == 0) {
                    v0 = fmaxf(v0, 0.f);
                    v1 = fmaxf(v1, 0.f);
                    *(__half2*)&g_actB[pix * 256 + oc] =
                        __halves2half2(__float2half_rn(v0), __float2half_rn(v1));
                } else {
                    float2 sk = *(const float2*)&g_skip[pix * 256 + oc];
                    v0 += sk.x;
                    v1 += sk.y;
                    if (MODE == 1) {
                        *(float2*)&g_skip[pix * 256 + oc] = make_float2(v0, v1);
                        *(__half2*)&g_actA[pix * 256 + oc] =
                            __halves2half2(__float2half_rn(v0), __float2half_rn(v1));
                    } else {
                        dout[((size_t)(b * C_ + oc) * HW_ + yout) * HW_ + px] = v0;
                        dout[((size_t)(b * C_ + oc + 1) * HW_ + yout) * HW_ + px] = v1;
                    }
                }
            }
        }
    }
}

// ---------------- launcher ----------------
extern "C" void kernel_launch(void* const* d_in, const int* in_sizes, int n_in,
                              void* d_out, int out_size) {
    const float* x        = (const float*)d_in[0];
    const float* gumbel_u = (const float*)d_in[1];
    const float* W_map    = (const float*)d_in[2];
    const float* proj_w   = (const float*)d_in[3];
    const float* proj_b   = (const float*)d_in[4];
    const float* embed    = (const float*)d_in[5];
    const float* res_w1   = (const float*)d_in[6];
    const float* res_b1   = (const float*)d_in[7];
    const float* res_w2   = (const float*)d_in[8];
    const float* res_b2   = (const float*)d_in[9];
    float* out = (float*)d_out;

    cudaFuncSetAttribute(conv_hmma<0>, cudaFuncAttributeMaxDynamicSharedMemorySize, SMEMSZ);
    cudaFuncSetAttribute(conv_hmma<1>, cudaFuncAttributeMaxDynamicSharedMemorySize, SMEMSZ);
    cudaFuncSetAttribute(conv_hmma<2>, cudaFuncAttributeMaxDynamicSharedMemorySize, SMEMSZ);

    pool_kernel<<<B_ * C_, 256>>>(x);
    piror_kernel<<<B_, 256>>>(W_map, proj_w, proj_b, embed, gumbel_u);
    input_prep<<<dim3(B_ * HW_, 4, 8), dim3(32, 8)>>>(x);
    weight_prep<<<(27 * 256 * 256) / 256, 256>>>(res_w1, res_w2);

    dim3 cg(HW_ / 2, 4, B_);
    for (int i = 0; i < 3; i++) {
        conv_hmma<0><<<cg, NTHR, SMEMSZ>>>(res_b1 + i * C_, nullptr, i);
        if (i < 2)
            conv_hmma<1><<<cg, NTHR, SMEMSZ>>>(res_b2 + i * C_, nullptr, i);
        else
            conv_hmma<2><<<cg, NTHR, SMEMSZ>>>(res_b2 + i * C_, out, i);
    }
}